// round 2
// baseline (speedup 1.0000x reference)
#include <cuda_runtime.h>

#define NN 100000
#define EE 1600000
#define EPSF 1e-12f

// ---------------- scratch (static device globals) ---------------------------
__device__ __align__(128) float g_outdeg[3][NN];
__device__ __align__(128) float g_indeg[3][NN];
__device__ __align__(128) int   g_cnt[3][NN];
__device__ __align__(128) int   g_rowptr[3][NN];
__device__ __align__(128) int   g_pos[3][NN];
__device__ __align__(128) int   g_csrc[3][EE];   // CSR: src per in-edge, grouped by dst
__device__ __align__(128) float g_cnw[3][EE];    // CSR: normalized weight per in-edge
__device__ __align__(128) float g_h[NN * 64];    // transformed features (gemm output)
__device__ __align__(128) float g_t1[NN * 64];   // layer-1 output
__device__ __align__(128) float g_t2[NN * 32];   // layer-2 output

// ---------------- zero counters/degrees for all 3 layers --------------------
__global__ void zero_kernel() {
    int i = blockIdx.x * blockDim.x + threadIdx.x;
    if (i >= NN) return;
#pragma unroll
    for (int l = 0; l < 3; l++) {
        g_outdeg[l][i] = 0.f;
        g_indeg[l][i]  = 0.f;
        g_cnt[l][i]    = 0;
    }
}

// ---------------- fused degree + histogram over all 3 edge lists ------------
__global__ void degcnt_kernel(const int* __restrict__ s1, const int* __restrict__ d1, const float* __restrict__ w1,
                              const int* __restrict__ s2, const int* __restrict__ d2, const float* __restrict__ w2,
                              const int* __restrict__ s3, const int* __restrict__ d3, const float* __restrict__ w3) {
    long long idx = (long long)blockIdx.x * blockDim.x + threadIdx.x;
    if (idx >= 3LL * EE) return;
    int layer = (int)(idx / EE);
    int e = (int)(idx - (long long)layer * EE);
    const int* src = layer == 0 ? s1 : layer == 1 ? s2 : s3;
    const int* dst = layer == 0 ? d1 : layer == 1 ? d2 : d3;
    const float* w = layer == 0 ? w1 : layer == 1 ? w2 : w3;
    int s = src[e], d = dst[e];
    float wv = w[e];
    atomicAdd(&g_outdeg[layer][s], wv);
    atomicAdd(&g_indeg[layer][d], wv);
    atomicAdd(&g_cnt[layer][d], 1);
}

// ---------------- exclusive scan of cnt -> rowptr & pos (1 block / layer) ---
__global__ void scan_kernel() {
    const int T = 1024;
    int layer = blockIdx.x;
    int tid = threadIdx.x;
    const int chunk = (NN + T - 1) / T;  // 98
    int begin = tid * chunk;
    int finish = min(begin + chunk, NN);

    int s = 0;
    for (int i = begin; i < finish; i++) s += g_cnt[layer][i];

    __shared__ int sh[T];
    sh[tid] = s;
    __syncthreads();
    for (int off = 1; off < T; off <<= 1) {
        int v = 0;
        if (tid >= off) v = sh[tid - off];
        __syncthreads();
        sh[tid] += v;
        __syncthreads();
    }
    int run = sh[tid] - s;  // exclusive offset for this thread's chunk
    for (int i = begin; i < finish; i++) {
        g_rowptr[layer][i] = run;
        g_pos[layer][i] = run;
        run += g_cnt[layer][i];
    }
}

// ---------------- CSR build: scatter (src, nw) into dst-grouped segments ----
__global__ void csr_build_kernel(const int* __restrict__ s1, const int* __restrict__ d1, const float* __restrict__ w1,
                                 const int* __restrict__ s2, const int* __restrict__ d2, const float* __restrict__ w2,
                                 const int* __restrict__ s3, const int* __restrict__ d3, const float* __restrict__ w3) {
    long long idx = (long long)blockIdx.x * blockDim.x + threadIdx.x;
    if (idx >= 3LL * EE) return;
    int layer = (int)(idx / EE);
    int e = (int)(idx - (long long)layer * EE);
    const int* src = layer == 0 ? s1 : layer == 1 ? s2 : s3;
    const int* dst = layer == 0 ? d1 : layer == 1 ? d2 : d3;
    const float* w = layer == 0 ? w1 : layer == 1 ? w2 : w3;
    int s = src[e], d = dst[e];
    float wv = w[e];
    float nw = wv * rsqrtf(fmaxf(g_outdeg[layer][s] * g_indeg[layer][d], EPSF));
    int p = atomicAdd(&g_pos[layer][d], 1);
    g_csrc[layer][p] = s;
    g_cnw[layer][p] = nw;
}

// ---------------- dense GEMM: g_h = in @ W (W in shared, 4 cols/thread) -----
// srcSel: 0 -> xext, 1 -> g_t1, 2 -> g_t2
template <int DIN, int DOUT>
__global__ void gemm_kernel(const float* __restrict__ xext,
                            const float* __restrict__ W, int srcSel) {
    __shared__ float sW[DIN * DOUT];
    for (int i = threadIdx.x; i < DIN * DOUT; i += blockDim.x) sW[i] = W[i];
    __syncthreads();

    const float* x = (srcSel == 0) ? xext : (srcSel == 1) ? g_t1 : g_t2;

    constexpr int TPR = DOUT / 4;  // threads per row
    const int rowsPerBlock = blockDim.x / TPR;
    int row = blockIdx.x * rowsPerBlock + threadIdx.x / TPR;
    int cg = (threadIdx.x % TPR) * 4;
    if (row >= NN) return;

    float a0 = 0.f, a1 = 0.f, a2 = 0.f, a3 = 0.f;
    const float4* x4 = reinterpret_cast<const float4*>(x + (size_t)row * DIN);
#pragma unroll
    for (int k4 = 0; k4 < DIN / 4; k4++) {
        float4 xv = __ldg(&x4[k4]);
#pragma unroll
        for (int j = 0; j < 4; j++) {
            float xs = (j == 0) ? xv.x : (j == 1) ? xv.y : (j == 2) ? xv.z : xv.w;
            const float4 wv = *reinterpret_cast<const float4*>(&sW[(k4 * 4 + j) * DOUT + cg]);
            a0 += xs * wv.x; a1 += xs * wv.y; a2 += xs * wv.z; a3 += xs * wv.w;
        }
    }
    float4* h4 = reinterpret_cast<float4*>(g_h + (size_t)row * DOUT);
    h4[cg / 4] = make_float4(a0, a1, a2, a3);
}

// ---------------- gather-aggregate + deg-divide + bias ----------------------
// One warp per dst node. Register accumulation, single row write.
// dstSel: 0 -> outext, 1 -> g_t1, 2 -> g_t2
template <int DOUT>
__global__ void gather_kernel(const float* __restrict__ b,
                              float* __restrict__ outext, int dstSel, int layer) {
    constexpr int FPL = DOUT / 32;  // floats per lane (2 for 64, 1 for 32)
    int warp = (blockIdx.x * blockDim.x + threadIdx.x) >> 5;
    if (warp >= NN) return;
    int lane = threadIdx.x & 31;

    int start = g_rowptr[layer][warp];
    int count = g_cnt[layer][warp];
    const int* __restrict__ csrc = g_csrc[layer];
    const float* __restrict__ cnw = g_cnw[layer];

    float acc0 = 0.f, acc1 = 0.f;
    float degsum = 0.f;

    for (int base = 0; base < count; base += 32) {
        int n = min(32, count - base);
        int s = 0;
        float nwv = 0.f;
        if (lane < n) {
            s = csrc[start + base + lane];
            nwv = cnw[start + base + lane];
        }
        degsum += nwv;
        for (int i = 0; i < n; i++) {
            int ss = __shfl_sync(0xffffffffu, s, i);
            float nn = __shfl_sync(0xffffffffu, nwv, i);
            const float* hrow = g_h + (size_t)ss * DOUT;
            if (FPL == 2) {
                float2 hv = *reinterpret_cast<const float2*>(hrow + lane * 2);
                acc0 += nn * hv.x;
                acc1 += nn * hv.y;
            } else {
                acc0 += nn * __ldg(&hrow[lane]);
            }
        }
    }

#pragma unroll
    for (int o = 16; o; o >>= 1) degsum += __shfl_xor_sync(0xffffffffu, degsum, o);
    float inv = 1.f / fmaxf(degsum, EPSF);

    float* out = (dstSel == 0) ? outext : (dstSel == 1) ? g_t1 : g_t2;
    if (FPL == 2) {
        float2 r;
        r.x = acc0 * inv + __ldg(&b[lane * 2]);
        r.y = acc1 * inv + __ldg(&b[lane * 2 + 1]);
        *reinterpret_cast<float2*>(out + (size_t)warp * DOUT + lane * 2) = r;
    } else {
        out[(size_t)warp * DOUT + lane] = acc0 * inv + __ldg(&b[lane]);
    }
}

// ---------------- launch ----------------------------------------------------
extern "C" void kernel_launch(void* const* d_in, const int* in_sizes, int n_in,
                              void* d_out, int out_size) {
    const float* x    = (const float*)d_in[0];
    const int*   src1 = (const int*)d_in[1];
    const int*   dst1 = (const int*)d_in[2];
    const float* w1   = (const float*)d_in[3];
    const int*   src2 = (const int*)d_in[4];
    const int*   dst2 = (const int*)d_in[5];
    const float* w2   = (const float*)d_in[6];
    const int*   src3 = (const int*)d_in[7];
    const int*   dst3 = (const int*)d_in[8];
    const float* w3   = (const float*)d_in[9];
    const float* W1   = (const float*)d_in[10];
    const float* b1   = (const float*)d_in[11];
    const float* W2   = (const float*)d_in[12];
    const float* b2   = (const float*)d_in[13];
    const float* W3   = (const float*)d_in[14];
    const float* b3   = (const float*)d_in[15];
    float* out = (float*)d_out;

    const int B = 256;
    const int gridN    = (NN + B - 1) / B;
    const int gridE3   = (3 * EE + B - 1) / B;
    const int gridWarp = (NN * 32 + B - 1) / B;  // 1 warp per node

    // Phase A: graph preprocessing (feature-independent, all 3 layers)
    zero_kernel<<<gridN, B>>>();
    degcnt_kernel<<<gridE3, B>>>(src1, dst1, w1, src2, dst2, w2, src3, dst3, w3);
    scan_kernel<<<3, 1024>>>();
    csr_build_kernel<<<gridE3, B>>>(src1, dst1, w1, src2, dst2, w2, src3, dst3, w3);

    // Phase B: layer pipeline (transform-first everywhere; /deg + bias fused in gather)
    gemm_kernel<128, 64><<<NN / (B / 16), B>>>(x, W1, 0);
    gather_kernel<64><<<gridWarp, B>>>(b1, nullptr, 1, 0);

    gemm_kernel<64, 32><<<NN / (B / 8), B>>>(nullptr, W2, 1);
    gather_kernel<32><<<gridWarp, B>>>(b2, nullptr, 2, 1);

    gemm_kernel<32, 32><<<NN / (B / 8), B>>>(nullptr, W3, 2);
    gather_kernel<32><<<gridWarp, B>>>(b3, out, 0, 2);

    (void)in_sizes; (void)n_in; (void)out_size;
}

// round 3
// speedup vs baseline: 1.5413x; 1.5413x over previous
#include <cuda_runtime.h>

#define NN 100000
#define EE 1600000
#define EPSF 1e-12f

// ---------------- scratch (static device globals) ---------------------------
__device__ __align__(128) float g_outdeg[3][NN];
__device__ __align__(128) float g_indeg[3][NN];
__device__ __align__(128) float g_deg[3][NN];
__device__ __align__(128) float g_h[NN * 64];        // transformed features
__device__ __align__(128) float g_agg64[NN * 64];    // layer-1 accumulator
__device__ __align__(128) float g_agg32[2][NN * 32]; // layer-2/3 accumulators
__device__ __align__(128) float g_t1[NN * 64];       // layer-1 output
__device__ __align__(128) float g_t2[NN * 32];       // layer-2 output

// ---------------- single fused zero pass ------------------------------------
__global__ void zero_kernel() {
    int i = blockIdx.x * blockDim.x + threadIdx.x;
    float4 z = make_float4(0.f, 0.f, 0.f, 0.f);
    if (i < NN * 16) reinterpret_cast<float4*>(g_agg64)[i] = z;
    if (i < NN * 8) {
        reinterpret_cast<float4*>(g_agg32[0])[i] = z;
        reinterpret_cast<float4*>(g_agg32[1])[i] = z;
    }
    if (i < NN) {
#pragma unroll
        for (int l = 0; l < 3; l++) {
            g_outdeg[l][i] = 0.f;
            g_indeg[l][i] = 0.f;
            g_deg[l][i] = 0.f;
        }
    }
}

// ---------------- fused weighted-degree sums for all 3 layers ---------------
__global__ void edge_deg_kernel(const int* __restrict__ s1, const int* __restrict__ d1, const float* __restrict__ w1,
                                const int* __restrict__ s2, const int* __restrict__ d2, const float* __restrict__ w2,
                                const int* __restrict__ s3, const int* __restrict__ d3, const float* __restrict__ w3) {
    long long idx = (long long)blockIdx.x * blockDim.x + threadIdx.x;
    if (idx >= 3LL * EE) return;
    int layer = (int)(idx / EE);
    int e = (int)(idx - (long long)layer * EE);
    const int* src = layer == 0 ? s1 : layer == 1 ? s2 : s3;
    const int* dst = layer == 0 ? d1 : layer == 1 ? d2 : d3;
    const float* w = layer == 0 ? w1 : layer == 1 ? w2 : w3;
    float wv = w[e];
    atomicAdd(&g_outdeg[layer][src[e]], wv);
    atomicAdd(&g_indeg[layer][dst[e]], wv);
}

// ---------------- dense GEMM: g_h = in @ W (W in shared, 4 cols/thread) -----
// srcSel: 0 -> xext, 1 -> g_t1, 2 -> g_t2
template <int DIN, int DOUT>
__global__ void gemm_kernel(const float* __restrict__ xext,
                            const float* __restrict__ W, int srcSel) {
    __shared__ float sW[DIN * DOUT];
    for (int i = threadIdx.x; i < DIN * DOUT; i += blockDim.x) sW[i] = W[i];
    __syncthreads();

    const float* x = (srcSel == 0) ? xext : (srcSel == 1) ? g_t1 : g_t2;

    constexpr int TPR = DOUT / 4;  // threads per row
    const int rowsPerBlock = blockDim.x / TPR;
    int row = blockIdx.x * rowsPerBlock + threadIdx.x / TPR;
    int cg = (threadIdx.x % TPR) * 4;
    if (row >= NN) return;

    float a0 = 0.f, a1 = 0.f, a2 = 0.f, a3 = 0.f;
    const float4* x4 = reinterpret_cast<const float4*>(x + (size_t)row * DIN);
#pragma unroll
    for (int k4 = 0; k4 < DIN / 4; k4++) {
        float4 xv = __ldg(&x4[k4]);
#pragma unroll
        for (int j = 0; j < 4; j++) {
            float xs = (j == 0) ? xv.x : (j == 1) ? xv.y : (j == 2) ? xv.z : xv.w;
            const float4 wv = *reinterpret_cast<const float4*>(&sW[(k4 * 4 + j) * DOUT + cg]);
            a0 += xs * wv.x; a1 += xs * wv.y; a2 += xs * wv.z; a3 += xs * wv.w;
        }
    }
    float4* h4 = reinterpret_cast<float4*>(g_h + (size_t)row * DOUT);
    h4[cg / 4] = make_float4(a0, a1, a2, a3);
}

// ---------------- fused norm + deg + vectorized scatter ---------------------
// 32 edges per warp. Payload: LPE lanes per edge, each lane ld.128 + red.v4.
// EE % 32 == 0, so no tail predicates needed.
template <int DOUT>
__global__ void scatter_kernel(const int* __restrict__ src,
                               const int* __restrict__ dst,
                               const float* __restrict__ w, int layer) {
    const int lane = threadIdx.x & 31;
    const int warpId = (blockIdx.x * blockDim.x + threadIdx.x) >> 5;
    const int base = warpId * 32;
    if (base >= EE) return;

    int e = base + lane;
    int s = src[e];
    int d = dst[e];
    float nw = w[e] * rsqrtf(fmaxf(g_outdeg[layer][s] * g_indeg[layer][d], EPSF));
    atomicAdd(&g_deg[layer][d], nw);

    float* agg = (DOUT == 64) ? g_agg64 : g_agg32[layer - 1];
    constexpr int LPE = DOUT / 4;   // lanes per edge (16 / 8)
    constexpr int EPI = 32 / LPE;   // edges per iteration (2 / 4)
    const int sub = lane / LPE;
    const int l = lane % LPE;

#pragma unroll 1
    for (int i = 0; i < 32; i += EPI) {
        int idx = i + sub;
        int ss = __shfl_sync(0xffffffffu, s, idx);
        int dd = __shfl_sync(0xffffffffu, d, idx);
        float nn = __shfl_sync(0xffffffffu, nw, idx);
        const float4 hv = *reinterpret_cast<const float4*>(g_h + (size_t)ss * DOUT + l * 4);
        float* p = agg + (size_t)dd * DOUT + l * 4;
        asm volatile("red.global.add.v4.f32 [%0], {%1,%2,%3,%4};"
                     :: "l"(p), "f"(hv.x * nn), "f"(hv.y * nn), "f"(hv.z * nn), "f"(hv.w * nn)
                     : "memory");
    }
}

// ---------------- finalize: out = agg / max(deg,eps) + b --------------------
// dstSel: 0 -> outext, 1 -> g_t1, 2 -> g_t2
template <int DOUT>
__global__ void finalize_kernel(const float* __restrict__ b,
                                float* __restrict__ outext, int dstSel, int layer) {
    int idx = blockIdx.x * blockDim.x + threadIdx.x;
    if (idx >= NN * DOUT) return;
    const float* agg = (DOUT == 64) ? g_agg64 : g_agg32[layer - 1];
    float* out = (dstSel == 0) ? outext : (dstSel == 1) ? g_t1 : g_t2;
    int i = idx / DOUT;
    int f = idx % DOUT;
    out[idx] = agg[idx] / fmaxf(g_deg[layer][i], EPSF) + __ldg(&b[f]);
}

// ---------------- launch ----------------------------------------------------
extern "C" void kernel_launch(void* const* d_in, const int* in_sizes, int n_in,
                              void* d_out, int out_size) {
    const float* x    = (const float*)d_in[0];
    const int*   src1 = (const int*)d_in[1];
    const int*   dst1 = (const int*)d_in[2];
    const float* w1   = (const float*)d_in[3];
    const int*   src2 = (const int*)d_in[4];
    const int*   dst2 = (const int*)d_in[5];
    const float* w2   = (const float*)d_in[6];
    const int*   src3 = (const int*)d_in[7];
    const int*   dst3 = (const int*)d_in[8];
    const float* w3   = (const float*)d_in[9];
    const float* W1   = (const float*)d_in[10];
    const float* b1   = (const float*)d_in[11];
    const float* W2   = (const float*)d_in[12];
    const float* b2   = (const float*)d_in[13];
    const float* W3   = (const float*)d_in[14];
    const float* b3   = (const float*)d_in[15];
    float* out = (float*)d_out;

    const int B = 256;
    const int gridZero = (NN * 16 + B - 1) / B;
    const int gridE3   = (3 * EE + B - 1) / B;
    const int gridScat = (EE / 32) / (B / 32);  // 6250, exact

    // Phase A: zero + all degree sums (feature-independent)
    zero_kernel<<<gridZero, B>>>();
    edge_deg_kernel<<<gridE3, B>>>(src1, dst1, w1, src2, dst2, w2, src3, dst3, w3);

    // ---- Layer 1: 128 -> 64 ----
    gemm_kernel<128, 64><<<NN / (B / 16), B>>>(x, W1, 0);
    scatter_kernel<64><<<gridScat, B>>>(src1, dst1, w1, 0);
    finalize_kernel<64><<<(NN * 64 + B - 1) / B, B>>>(b1, nullptr, 1, 0);

    // ---- Layer 2: 64 -> 32 ----
    gemm_kernel<64, 32><<<NN / (B / 8), B>>>(nullptr, W2, 1);
    scatter_kernel<32><<<gridScat, B>>>(src2, dst2, w2, 1);
    finalize_kernel<32><<<(NN * 32 + B - 1) / B, B>>>(b2, nullptr, 2, 1);

    // ---- Layer 3: 32 -> 32 ----
    gemm_kernel<32, 32><<<NN / (B / 8), B>>>(nullptr, W3, 2);
    scatter_kernel<32><<<gridScat, B>>>(src3, dst3, w3, 2);
    finalize_kernel<32><<<(NN * 32 + B - 1) / B, B>>>(b3, out, 0, 2);

    (void)in_sizes; (void)n_in; (void)out_size;
}

// round 7
// speedup vs baseline: 1.6599x; 1.0769x over previous
#include <cuda_runtime.h>
#include <cuda_fp16.h>

#define NN 100000
#define EE 1600000
#define EPSF 1e-12f

// ---------------- bit-cast helpers ------------------------------------------
__device__ __forceinline__ unsigned int h2_to_u32(__half2 v) {
    return *reinterpret_cast<unsigned int*>(&v);
}
__device__ __forceinline__ __half2 u32_to_h2(unsigned int u) {
    return *reinterpret_cast<__half2*>(&u);
}

// ---------------- scratch (static device globals) ---------------------------
__device__ __align__(128) float g_outdeg[3][NN];
__device__ __align__(128) float g_indeg[3][NN];
__device__ __align__(128) float g_deg[3][NN];
__device__ __align__(128) __half g_hh[NN * 64];      // transformed features (fp16)
__device__ __align__(128) float g_agg64[NN * 64];    // layer-1 accumulator
__device__ __align__(128) float g_agg32[2][NN * 32]; // layer-2/3 accumulators

// ---------------- single fused zero pass ------------------------------------
__global__ void zero_kernel() {
    int i = blockIdx.x * blockDim.x + threadIdx.x;
    float4 z = make_float4(0.f, 0.f, 0.f, 0.f);
    if (i < NN * 16) reinterpret_cast<float4*>(g_agg64)[i] = z;
    if (i < NN * 8) {
        reinterpret_cast<float4*>(g_agg32[0])[i] = z;
        reinterpret_cast<float4*>(g_agg32[1])[i] = z;
    }
    if (i < NN) {
#pragma unroll
        for (int l = 0; l < 3; l++) {
            g_outdeg[l][i] = 0.f;
            g_indeg[l][i] = 0.f;
            g_deg[l][i] = 0.f;
        }
    }
}

// ---------------- fused weighted-degree sums for all 3 layers ---------------
__global__ void edge_deg_kernel(const int* __restrict__ s1, const int* __restrict__ d1, const float* __restrict__ w1,
                                const int* __restrict__ s2, const int* __restrict__ d2, const float* __restrict__ w2,
                                const int* __restrict__ s3, const int* __restrict__ d3, const float* __restrict__ w3) {
    long long idx = (long long)blockIdx.x * blockDim.x + threadIdx.x;
    if (idx >= 3LL * EE) return;
    int layer = (int)(idx / EE);
    int e = (int)(idx - (long long)layer * EE);
    const int* src = layer == 0 ? s1 : layer == 1 ? s2 : s3;
    const int* dst = layer == 0 ? d1 : layer == 1 ? d2 : d3;
    const float* w = layer == 0 ? w1 : layer == 1 ? w2 : w3;
    float wv = w[e];
    atomicAdd(&g_outdeg[layer][src[e]], wv);
    atomicAdd(&g_indeg[layer][dst[e]], wv);
}

// ---------------- layer-1 GEMM: g_hh = x @ W1 (fp32 in, fp16 out) -----------
template <int DIN, int DOUT>
__global__ void gemm1_kernel(const float* __restrict__ x, const float* __restrict__ W) {
    __shared__ float sW[DIN * DOUT];
    for (int i = threadIdx.x; i < DIN * DOUT; i += blockDim.x) sW[i] = W[i];
    __syncthreads();

    constexpr int TPR = DOUT / 4;
    const int rowsPerBlock = blockDim.x / TPR;
    int row = blockIdx.x * rowsPerBlock + threadIdx.x / TPR;
    int cg = (threadIdx.x % TPR) * 4;
    if (row >= NN) return;

    float a0 = 0.f, a1 = 0.f, a2 = 0.f, a3 = 0.f;
    const float4* x4 = reinterpret_cast<const float4*>(x + (size_t)row * DIN);
#pragma unroll
    for (int k4 = 0; k4 < DIN / 4; k4++) {
        float4 xv = __ldg(&x4[k4]);
#pragma unroll
        for (int j = 0; j < 4; j++) {
            float xs = (j == 0) ? xv.x : (j == 1) ? xv.y : (j == 2) ? xv.z : xv.w;
            const float4 wv = *reinterpret_cast<const float4*>(&sW[(k4 * 4 + j) * DOUT + cg]);
            a0 += xs * wv.x; a1 += xs * wv.y; a2 += xs * wv.z; a3 += xs * wv.w;
        }
    }
    uint2 pk;
    pk.x = h2_to_u32(__floats2half2_rn(a0, a1));
    pk.y = h2_to_u32(__floats2half2_rn(a2, a3));
    *reinterpret_cast<uint2*>(g_hh + (size_t)row * DOUT + cg) = pk;
}

// ---------------- fused finalize + GEMM (layers 2 & 3) ----------------------
// t = agg/deg + bIn  (fp32, in registers), then g_hh = t @ W (fp16 out)
template <int DIN, int DOUT>
__global__ void gemm_fused_kernel(const float* __restrict__ agg,
                                  const float* __restrict__ deg,
                                  const float* __restrict__ bIn,
                                  const float* __restrict__ W) {
    __shared__ float sW[DIN * DOUT];
    __shared__ float sB[DIN];
    for (int i = threadIdx.x; i < DIN * DOUT; i += blockDim.x) sW[i] = W[i];
    for (int i = threadIdx.x; i < DIN; i += blockDim.x) sB[i] = bIn[i];
    __syncthreads();

    constexpr int TPR = DOUT / 4;
    const int rowsPerBlock = blockDim.x / TPR;
    int row = blockIdx.x * rowsPerBlock + threadIdx.x / TPR;
    int cg = (threadIdx.x % TPR) * 4;
    if (row >= NN) return;

    float inv = 1.f / fmaxf(deg[row], EPSF);
    float a0 = 0.f, a1 = 0.f, a2 = 0.f, a3 = 0.f;
    const float4* x4 = reinterpret_cast<const float4*>(agg + (size_t)row * DIN);
#pragma unroll
    for (int k4 = 0; k4 < DIN / 4; k4++) {
        float4 xv = __ldg(&x4[k4]);
        xv.x = xv.x * inv + sB[k4 * 4 + 0];
        xv.y = xv.y * inv + sB[k4 * 4 + 1];
        xv.z = xv.z * inv + sB[k4 * 4 + 2];
        xv.w = xv.w * inv + sB[k4 * 4 + 3];
#pragma unroll
        for (int j = 0; j < 4; j++) {
            float xs = (j == 0) ? xv.x : (j == 1) ? xv.y : (j == 2) ? xv.z : xv.w;
            const float4 wv = *reinterpret_cast<const float4*>(&sW[(k4 * 4 + j) * DOUT + cg]);
            a0 += xs * wv.x; a1 += xs * wv.y; a2 += xs * wv.z; a3 += xs * wv.w;
        }
    }
    uint2 pk;
    pk.x = h2_to_u32(__floats2half2_rn(a0, a1));
    pk.y = h2_to_u32(__floats2half2_rn(a2, a3));
    *reinterpret_cast<uint2*>(g_hh + (size_t)row * DOUT + cg) = pk;
}

// ---------------- fused norm + deg + vectorized fp16-gather scatter ---------
// 32 edges per warp. LPE lanes per edge: 8B fp16 load -> fp32 red.v4 (16B).
template <int DOUT>
__global__ void scatter_kernel(const int* __restrict__ src,
                               const int* __restrict__ dst,
                               const float* __restrict__ w, int layer) {
    const int lane = threadIdx.x & 31;
    const int warpId = (blockIdx.x * blockDim.x + threadIdx.x) >> 5;
    const int base = warpId * 32;
    if (base >= EE) return;

    int e = base + lane;
    int s = src[e];
    int d = dst[e];
    float nw = w[e] * rsqrtf(fmaxf(g_outdeg[layer][s] * g_indeg[layer][d], EPSF));
    atomicAdd(&g_deg[layer][d], nw);

    float* agg = (DOUT == 64) ? g_agg64 : g_agg32[layer - 1];
    constexpr int LPE = DOUT / 4;   // lanes per edge (16 / 8)
    constexpr int EPI = 32 / LPE;   // edges per iteration (2 / 4)
    const int sub = lane / LPE;
    const int l = lane % LPE;

#pragma unroll 4
    for (int i = 0; i < 32; i += EPI) {
        int idx = i + sub;
        int ss = __shfl_sync(0xffffffffu, s, idx);
        int dd = __shfl_sync(0xffffffffu, d, idx);
        float nn = __shfl_sync(0xffffffffu, nw, idx);
        uint2 hv = *reinterpret_cast<const uint2*>(g_hh + (size_t)ss * DOUT + l * 4);
        float2 f0 = __half22float2(u32_to_h2(hv.x));
        float2 f1 = __half22float2(u32_to_h2(hv.y));
        float* p = agg + (size_t)dd * DOUT + l * 4;
        asm volatile("red.global.add.v4.f32 [%0], {%1,%2,%3,%4};"
                     :: "l"(p), "f"(f0.x * nn), "f"(f0.y * nn), "f"(f1.x * nn), "f"(f1.y * nn)
                     : "memory");
    }
}

// ---------------- final output: out = agg / max(deg,eps) + b ----------------
__global__ void final_kernel(const float* __restrict__ b, float* __restrict__ out) {
    int idx = blockIdx.x * blockDim.x + threadIdx.x;  // one float4 per thread
    if (idx >= NN * 8) return;
    int i = idx / 8;       // node
    int f4 = idx % 8;      // float4 slot within 32
    float inv = 1.f / fmaxf(g_deg[2][i], EPSF);
    float4 a = reinterpret_cast<const float4*>(g_agg32[1])[idx];
    float4 r;
    r.x = a.x * inv + __ldg(&b[f4 * 4 + 0]);
    r.y = a.y * inv + __ldg(&b[f4 * 4 + 1]);
    r.z = a.z * inv + __ldg(&b[f4 * 4 + 2]);
    r.w = a.w * inv + __ldg(&b[f4 * 4 + 3]);
    reinterpret_cast<float4*>(out)[idx] = r;
}

// ---------------- launch ----------------------------------------------------
extern "C" void kernel_launch(void* const* d_in, const int* in_sizes, int n_in,
                              void* d_out, int out_size) {
    const float* x    = (const float*)d_in[0];
    const int*   src1 = (const int*)d_in[1];
    const int*   dst1 = (const int*)d_in[2];
    const float* w1   = (const float*)d_in[3];
    const int*   src2 = (const int*)d_in[4];
    const int*   dst2 = (const int*)d_in[5];
    const float* w2   = (const float*)d_in[6];
    const int*   src3 = (const int*)d_in[7];
    const int*   dst3 = (const int*)d_in[8];
    const float* w3   = (const float*)d_in[9];
    const float* W1   = (const float*)d_in[10];
    const float* b1   = (const float*)d_in[11];
    const float* W2   = (const float*)d_in[12];
    const float* b2   = (const float*)d_in[13];
    const float* W3   = (const float*)d_in[14];
    const float* b3   = (const float*)d_in[15];
    float* out = (float*)d_out;

    // Host-side symbol address query: no allocation, no sync, graph-capture safe.
    static float* p_agg64 = nullptr;
    static float* p_agg32_0 = nullptr;
    static float* p_deg0 = nullptr;
    static float* p_deg1 = nullptr;
    if (!p_agg64) {
        cudaGetSymbolAddress((void**)&p_agg64, g_agg64);
        cudaGetSymbolAddress((void**)&p_agg32_0, g_agg32);
        cudaGetSymbolAddress((void**)&p_deg0, g_deg);
        p_deg1 = p_deg0 + NN;
    }

    const int B = 256;
    const int gridZero = (NN * 16 + B - 1) / B;
    const int gridE3   = (3 * EE + B - 1) / B;
    const int gridScat = (EE / 32) / (B / 32);  // 6250, exact

    // Phase A: zero + all degree sums (feature-independent)
    zero_kernel<<<gridZero, B>>>();
    edge_deg_kernel<<<gridE3, B>>>(src1, dst1, w1, src2, dst2, w2, src3, dst3, w3);

    // ---- Layer 1: 128 -> 64 ----
    gemm1_kernel<128, 64><<<NN / 16, B>>>(x, W1);
    scatter_kernel<64><<<gridScat, B>>>(src1, dst1, w1, 0);

    // ---- Layer 2: 64 -> 32 (finalize-1 fused) ----
    gemm_fused_kernel<64, 32><<<NN / 32, B>>>(p_agg64, p_deg0, b1, W2);
    scatter_kernel<32><<<gridScat, B>>>(src2, dst2, w2, 1);

    // ---- Layer 3: 32 -> 32 (finalize-2 fused) ----
    gemm_fused_kernel<32, 32><<<NN / 32, B>>>(p_agg32_0, p_deg1, b2, W3);
    scatter_kernel<32><<<gridScat, B>>>(src3, dst3, w3, 2);

    // ---- Output ----
    final_kernel<<<(NN * 8 + B - 1) / B, B>>>(b3, out);

    (void)in_sizes; (void)n_in; (void)out_size;
}

// round 8
// speedup vs baseline: 1.6762x; 1.0099x over previous
#include <cuda_runtime.h>
#include <cuda_fp16.h>

#define NN 100000
#define EE 1600000
#define EPSF 1e-12f

// ---------------- bit-cast helpers ------------------------------------------
__device__ __forceinline__ unsigned int h2_to_u32(__half2 v) {
    return *reinterpret_cast<unsigned int*>(&v);
}
__device__ __forceinline__ __half2 u32_to_h2(unsigned int u) {
    return *reinterpret_cast<__half2*>(&u);
}

// ---------------- scratch (static device globals) ---------------------------
__device__ __align__(128) float g_outdeg[3][NN];
__device__ __align__(128) float g_indeg[3][NN];
__device__ __align__(128) float g_deg[3][NN];
__device__ __align__(128) __half g_hh[NN * 64];      // transformed features (fp16)
__device__ __align__(128) float g_agg64[NN * 64];    // layer-1 accumulator
__device__ __align__(128) float g_agg32[2][NN * 32]; // layer-2/3 accumulators

// ---------------- single fused zero pass ------------------------------------
__global__ void zero_kernel() {
    int i = blockIdx.x * blockDim.x + threadIdx.x;
    float4 z = make_float4(0.f, 0.f, 0.f, 0.f);
    if (i < NN * 16) reinterpret_cast<float4*>(g_agg64)[i] = z;
    if (i < NN * 8) {
        reinterpret_cast<float4*>(g_agg32[0])[i] = z;
        reinterpret_cast<float4*>(g_agg32[1])[i] = z;
    }
    if (i < NN) {
#pragma unroll
        for (int l = 0; l < 3; l++) {
            g_outdeg[l][i] = 0.f;
            g_indeg[l][i] = 0.f;
            g_deg[l][i] = 0.f;
        }
    }
}

// ---------------- weighted-degree sums: one layer ---------------------------
__global__ void edge_deg1_kernel(const int* __restrict__ src, const int* __restrict__ dst,
                                 const float* __restrict__ w, int layer) {
    int e = blockIdx.x * blockDim.x + threadIdx.x;
    if (e >= EE) return;
    float wv = w[e];
    atomicAdd(&g_outdeg[layer][src[e]], wv);
    atomicAdd(&g_indeg[layer][dst[e]], wv);
}

// ---------------- weighted-degree sums: layers 2 & 3 ------------------------
__global__ void edge_deg23_kernel(const int* __restrict__ s2, const int* __restrict__ d2, const float* __restrict__ w2,
                                  const int* __restrict__ s3, const int* __restrict__ d3, const float* __restrict__ w3) {
    int idx = blockIdx.x * blockDim.x + threadIdx.x;
    if (idx >= 2 * EE) return;
    int layer = 1 + (idx >= EE);
    int e = (idx >= EE) ? idx - EE : idx;
    const int* src = (layer == 1) ? s2 : s3;
    const int* dst = (layer == 1) ? d2 : d3;
    const float* w = (layer == 1) ? w2 : w3;
    float wv = w[e];
    atomicAdd(&g_outdeg[layer][src[e]], wv);
    atomicAdd(&g_indeg[layer][dst[e]], wv);
}

// ---------------- layer-1 GEMM: g_hh = x @ W1 (fp32 in, fp16 out) -----------
template <int DIN, int DOUT>
__global__ void gemm1_kernel(const float* __restrict__ x, const float* __restrict__ W) {
    __shared__ float sW[DIN * DOUT];
    for (int i = threadIdx.x; i < DIN * DOUT; i += blockDim.x) sW[i] = W[i];
    __syncthreads();

    constexpr int TPR = DOUT / 4;
    const int rowsPerBlock = blockDim.x / TPR;
    int row = blockIdx.x * rowsPerBlock + threadIdx.x / TPR;
    int cg = (threadIdx.x % TPR) * 4;
    if (row >= NN) return;

    float a0 = 0.f, a1 = 0.f, a2 = 0.f, a3 = 0.f;
    const float4* x4 = reinterpret_cast<const float4*>(x + (size_t)row * DIN);
#pragma unroll
    for (int k4 = 0; k4 < DIN / 4; k4++) {
        float4 xv = __ldg(&x4[k4]);
#pragma unroll
        for (int j = 0; j < 4; j++) {
            float xs = (j == 0) ? xv.x : (j == 1) ? xv.y : (j == 2) ? xv.z : xv.w;
            const float4 wv = *reinterpret_cast<const float4*>(&sW[(k4 * 4 + j) * DOUT + cg]);
            a0 += xs * wv.x; a1 += xs * wv.y; a2 += xs * wv.z; a3 += xs * wv.w;
        }
    }
    uint2 pk;
    pk.x = h2_to_u32(__floats2half2_rn(a0, a1));
    pk.y = h2_to_u32(__floats2half2_rn(a2, a3));
    *reinterpret_cast<uint2*>(g_hh + (size_t)row * DOUT + cg) = pk;
}

// ---------------- fused finalize + GEMM (layers 2 & 3) ----------------------
// t = agg/deg + bIn  (fp32, in registers), then g_hh = t @ W (fp16 out)
template <int DIN, int DOUT>
__global__ void gemm_fused_kernel(const float* __restrict__ agg,
                                  const float* __restrict__ deg,
                                  const float* __restrict__ bIn,
                                  const float* __restrict__ W) {
    __shared__ float sW[DIN * DOUT];
    __shared__ float sB[DIN];
    for (int i = threadIdx.x; i < DIN * DOUT; i += blockDim.x) sW[i] = W[i];
    for (int i = threadIdx.x; i < DIN; i += blockDim.x) sB[i] = bIn[i];
    __syncthreads();

    constexpr int TPR = DOUT / 4;
    const int rowsPerBlock = blockDim.x / TPR;
    int row = blockIdx.x * rowsPerBlock + threadIdx.x / TPR;
    int cg = (threadIdx.x % TPR) * 4;
    if (row >= NN) return;

    float inv = 1.f / fmaxf(deg[row], EPSF);
    float a0 = 0.f, a1 = 0.f, a2 = 0.f, a3 = 0.f;
    const float4* x4 = reinterpret_cast<const float4*>(agg + (size_t)row * DIN);
#pragma unroll
    for (int k4 = 0; k4 < DIN / 4; k4++) {
        float4 xv = __ldg(&x4[k4]);
        xv.x = xv.x * inv + sB[k4 * 4 + 0];
        xv.y = xv.y * inv + sB[k4 * 4 + 1];
        xv.z = xv.z * inv + sB[k4 * 4 + 2];
        xv.w = xv.w * inv + sB[k4 * 4 + 3];
#pragma unroll
        for (int j = 0; j < 4; j++) {
            float xs = (j == 0) ? xv.x : (j == 1) ? xv.y : (j == 2) ? xv.z : xv.w;
            const float4 wv = *reinterpret_cast<const float4*>(&sW[(k4 * 4 + j) * DOUT + cg]);
            a0 += xs * wv.x; a1 += xs * wv.y; a2 += xs * wv.z; a3 += xs * wv.w;
        }
    }
    uint2 pk;
    pk.x = h2_to_u32(__floats2half2_rn(a0, a1));
    pk.y = h2_to_u32(__floats2half2_rn(a2, a3));
    *reinterpret_cast<uint2*>(g_hh + (size_t)row * DOUT + cg) = pk;
}

// ---------------- fused norm + deg + vectorized fp16-gather scatter ---------
// 32 edges per warp. LPE lanes per edge: 8B fp16 load -> fp32 red.v4 (16B).
template <int DOUT>
__global__ void scatter_kernel(const int* __restrict__ src,
                               const int* __restrict__ dst,
                               const float* __restrict__ w, int layer) {
    const int lane = threadIdx.x & 31;
    const int warpId = (blockIdx.x * blockDim.x + threadIdx.x) >> 5;
    const int base = warpId * 32;
    if (base >= EE) return;

    int e = base + lane;
    int s = src[e];
    int d = dst[e];
    float nw = w[e] * rsqrtf(fmaxf(g_outdeg[layer][s] * g_indeg[layer][d], EPSF));
    atomicAdd(&g_deg[layer][d], nw);

    float* agg = (DOUT == 64) ? g_agg64 : g_agg32[layer - 1];
    constexpr int LPE = DOUT / 4;   // lanes per edge (16 / 8)
    constexpr int EPI = 32 / LPE;   // edges per iteration (2 / 4)
    const int sub = lane / LPE;
    const int l = lane % LPE;

#pragma unroll 4
    for (int i = 0; i < 32; i += EPI) {
        int idx = i + sub;
        int ss = __shfl_sync(0xffffffffu, s, idx);
        int dd = __shfl_sync(0xffffffffu, d, idx);
        float nn = __shfl_sync(0xffffffffu, nw, idx);
        uint2 hv = *reinterpret_cast<const uint2*>(g_hh + (size_t)ss * DOUT + l * 4);
        float2 f0 = __half22float2(u32_to_h2(hv.x));
        float2 f1 = __half22float2(u32_to_h2(hv.y));
        float* p = agg + (size_t)dd * DOUT + l * 4;
        asm volatile("red.global.add.v4.f32 [%0], {%1,%2,%3,%4};"
                     :: "l"(p), "f"(f0.x * nn), "f"(f0.y * nn), "f"(f1.x * nn), "f"(f1.y * nn)
                     : "memory");
    }
}

// ---------------- final output: out = agg / max(deg,eps) + b ----------------
__global__ void final_kernel(const float* __restrict__ b, float* __restrict__ out) {
    int idx = blockIdx.x * blockDim.x + threadIdx.x;  // one float4 per thread
    if (idx >= NN * 8) return;
    int i = idx / 8;       // node
    int f4 = idx % 8;      // float4 slot within 32
    float inv = 1.f / fmaxf(g_deg[2][i], EPSF);
    float4 a = reinterpret_cast<const float4*>(g_agg32[1])[idx];
    float4 r;
    r.x = a.x * inv + __ldg(&b[f4 * 4 + 0]);
    r.y = a.y * inv + __ldg(&b[f4 * 4 + 1]);
    r.z = a.z * inv + __ldg(&b[f4 * 4 + 2]);
    r.w = a.w * inv + __ldg(&b[f4 * 4 + 3]);
    reinterpret_cast<float4*>(out)[idx] = r;
}

// ---------------- launch ----------------------------------------------------
extern "C" void kernel_launch(void* const* d_in, const int* in_sizes, int n_in,
                              void* d_out, int out_size) {
    const float* x    = (const float*)d_in[0];
    const int*   src1 = (const int*)d_in[1];
    const int*   dst1 = (const int*)d_in[2];
    const float* w1   = (const float*)d_in[3];
    const int*   src2 = (const int*)d_in[4];
    const int*   dst2 = (const int*)d_in[5];
    const float* w2   = (const float*)d_in[6];
    const int*   src3 = (const int*)d_in[7];
    const int*   dst3 = (const int*)d_in[8];
    const float* w3   = (const float*)d_in[9];
    const float* W1   = (const float*)d_in[10];
    const float* b1   = (const float*)d_in[11];
    const float* W2   = (const float*)d_in[12];
    const float* b2   = (const float*)d_in[13];
    const float* W3   = (const float*)d_in[14];
    const float* b3   = (const float*)d_in[15];
    float* out = (float*)d_out;

    // One-time host-side setup (first call = correctness run, outside capture).
    static float* p_agg64 = nullptr;
    static float* p_agg32_0 = nullptr;
    static float* p_deg0 = nullptr;
    static float* p_deg1 = nullptr;
    static cudaStream_t s2 = nullptr;
    static cudaEvent_t evFork = nullptr, evZero = nullptr, evGemm1 = nullptr, evDeg23 = nullptr;
    if (!p_agg64) {
        cudaGetSymbolAddress((void**)&p_agg64, g_agg64);
        cudaGetSymbolAddress((void**)&p_agg32_0, g_agg32);
        cudaGetSymbolAddress((void**)&p_deg0, g_deg);
        p_deg1 = p_deg0 + NN;
        cudaStreamCreateWithFlags(&s2, cudaStreamNonBlocking);
        cudaEventCreateWithFlags(&evFork, cudaEventDisableTiming);
        cudaEventCreateWithFlags(&evZero, cudaEventDisableTiming);
        cudaEventCreateWithFlags(&evGemm1, cudaEventDisableTiming);
        cudaEventCreateWithFlags(&evDeg23, cudaEventDisableTiming);
    }

    const int B = 256;
    const int gridZero = (NN * 16 + B - 1) / B;
    const int gridE1   = (EE + B - 1) / B;
    const int gridE2   = (2 * EE + B - 1) / B;
    const int gridScat = (EE / 32) / (B / 32);  // 6250, exact

    // ---- Fork side stream (joins capture via event dependency) ----
    cudaEventRecord(evFork, 0);
    cudaStreamWaitEvent(s2, evFork, 0);

    // s2: gemm1 (depends only on x, W1)
    gemm1_kernel<128, 64><<<NN / 16, B, 0, s2>>>(x, W1);
    cudaEventRecord(evGemm1, s2);

    // main: zero + layer-1 degrees
    zero_kernel<<<gridZero, B>>>();
    cudaEventRecord(evZero, 0);
    edge_deg1_kernel<<<gridE1, B>>>(src1, dst1, w1, 0);

    // s2: layer-2/3 degrees (after zero), overlaps scatter1 on main
    cudaStreamWaitEvent(s2, evZero, 0);
    edge_deg23_kernel<<<gridE2, B, 0, s2>>>(src2, dst2, w2, src3, dst3, w3);
    cudaEventRecord(evDeg23, s2);

    // ---- Layer 1: 128 -> 64 ----
    cudaStreamWaitEvent(0, evGemm1, 0);
    scatter_kernel<64><<<gridScat, B>>>(src1, dst1, w1, 0);

    // ---- Layer 2: 64 -> 32 (finalize-1 fused) ----
    gemm_fused_kernel<64, 32><<<NN / 32, B>>>(p_agg64, p_deg0, b1, W2);
    cudaStreamWaitEvent(0, evDeg23, 0);
    scatter_kernel<32><<<gridScat, B>>>(src2, dst2, w2, 1);

    // ---- Layer 3: 32 -> 32 (finalize-2 fused) ----
    gemm_fused_kernel<32, 32><<<NN / 32, B>>>(p_agg32_0, p_deg1, b2, W3);
    scatter_kernel<32><<<gridScat, B>>>(src3, dst3, w3, 2);

    // ---- Output ----
    final_kernel<<<(NN * 8 + B - 1) / B, B>>>(b3, out);

    (void)in_sizes; (void)n_in; (void)out_size;
}